// round 12
// baseline (speedup 1.0000x reference)
#include <cuda_runtime.h>
#include <cuda_bf16.h>
#include <math.h>
#include <stdint.h>
#include <string.h>

#define BB 8
#define LL 1024
#define DD 768
#define MAXF 512   // nF <= 512
#define KEXP 1536  // [hi | lo] split-bf16 storage (2*DD)
#define ROWB 3072  // bytes per row (KEXP * 2)
#define SEGB 1536  // bytes per segment (DD * 2)
#define NITER 48   // 768 / 16 original-K per iter
#define PADK 40    // smem row stride in bf16 (80 bytes)
#define BUFB (128 * PADK * 2)  // bytes per smem buffer (10240)

// ---------------- scratch (device statics; no allocation) ----------------
__device__ int   g_nF[BB], g_nO[BB];
__device__ int   g_fIdx[BB][MAXF];
__device__ int   g_oIdx[BB][LL];
__device__ float g_gate[BB][MAXF];
__device__ __nv_bfloat16 g_Xexp[BB][LL][KEXP];        // [hi | lo]
__device__ __nv_bfloat16 g_Wexp[6][DD][KEXP];         // W^T rows, [hi | lo]
__device__ __nv_bfloat16 g_Qexp[3][BB][MAXF][KEXP];   // [hi | lo]
__device__ __nv_bfloat16 g_Koexp[3][BB][LL][KEXP];    // [hi | lo]
__device__ float g_Ssup[BB][MAXF][LL];
__device__ float g_Scon[BB][MAXF][LL];
__device__ float g_Srep[BB][MAXF][LL];
__device__ float g_Wsup[BB][LL];
__device__ float g_Wrep[BB][LL];
__device__ float g_WsupP[8][BB][LL];
__device__ float g_WrepP[8][BB][LL];
__device__ float g_fusedP[BB][3][8][DD];
__device__ float g_fused[BB][3 * DD];
__device__ float g_h1[BB][DD];

struct ProjPtrs { const float* W[6]; const float* bias[6]; };

// ---------------- helpers ----------------
__device__ __forceinline__ uint32_t smem_u32(const void* p) {
    return (uint32_t)__cvta_generic_to_shared(p);
}
__device__ __forceinline__ void ldsm_x4(uint32_t r[4], uint32_t addr) {
    asm volatile("ldmatrix.sync.aligned.m8n8.x4.shared.b16 {%0,%1,%2,%3}, [%4];"
                 : "=r"(r[0]), "=r"(r[1]), "=r"(r[2]), "=r"(r[3]) : "r"(addr));
}
__device__ __forceinline__ void mma_bf16(float c[4], const uint32_t a[4], const uint32_t b[2]) {
    asm volatile("mma.sync.aligned.m16n8k16.row.col.f32.bf16.bf16.f32 "
                 "{%0,%1,%2,%3}, {%4,%5,%6,%7}, {%8,%9}, {%0,%1,%2,%3};"
                 : "+f"(c[0]), "+f"(c[1]), "+f"(c[2]), "+f"(c[3])
                 : "r"(a[0]), "r"(a[1]), "r"(a[2]), "r"(a[3]), "r"(b[0]), "r"(b[1]));
}
__device__ __forceinline__ uint32_t packbf(float v0, float v1) {
    __nv_bfloat162 t = __floats2bfloat162_rn(v0, v1);
    uint32_t u;
    memcpy(&u, &t, 4);
    return u;
}
__device__ __forceinline__ void cp16(uint32_t dst, const void* src) {
    asm volatile("cp.async.cg.shared.global [%0], [%1], 16;" :: "r"(dst), "l"(src));
}
__device__ __forceinline__ void cp_commit() {
    asm volatile("cp.async.commit_group;" ::: "memory");
}
template <int N>
__device__ __forceinline__ void cp_wait() {
    asm volatile("cp.async.wait_group %0;" :: "n"(N) : "memory");
}

// ---------------- K1a: masks + compaction ----------------
__global__ void mask_kernel(const int* __restrict__ x_ids,
                            const int* __restrict__ pad_p) {
    int b = blockIdx.x;
    int tid = threadIdx.x;           // 256 threads
    __shared__ unsigned char s_valid[LL];
    __shared__ int s_ired[256];
    int pad = *pad_p;
    int cnt = 0;
    for (int i = tid; i < LL; i += 256) {
        int v = (x_ids[b * LL + i] != pad) ? 1 : 0;
        s_valid[i] = (unsigned char)v;
        cnt += v;
    }
    s_ired[tid] = cnt;
    __syncthreads();
    for (int s = 128; s > 0; s >>= 1) {
        if (tid < s) s_ired[tid] += s_ired[tid + s];
        __syncthreads();
    }
    int vl = s_ired[0];
    int sep = vl / 2;
    if (sep < 1) sep = 1;
    if (sep > LL - 2) sep = LL - 2;
    if (tid == 0) {
        int nf = 0, no = 0;
        for (int i = 0; i < LL; i++) {
            if (s_valid[i]) {
                if (i < sep)      g_fIdx[b][nf++] = i;
                else if (i > sep) g_oIdx[b][no++] = i;
            }
        }
        g_nF[b] = nf;
        g_nO[b] = no;
    }
}

// ---------------- K1b: anomaly logits (raw, into g_gate) ----------------
__global__ void logit_kernel(const float* __restrict__ x,
                             const float* __restrict__ Wa,
                             const float* __restrict__ ba) {
    int b = blockIdx.x;
    int r = blockIdx.y * 256 + threadIdx.x;
    __shared__ float s_Wa[DD];
    for (int i = threadIdx.x; i < DD; i += 256) s_Wa[i] = Wa[i];
    __syncthreads();
    if (r >= g_nF[b]) return;
    const float* xr = x + ((size_t)b * LL + g_fIdx[b][r]) * DD;
    float acc = ba[0];
    #pragma unroll 8
    for (int k = 0; k < DD; k++) acc += xr[k] * s_Wa[k];
    g_gate[b][r] = acc;
}

// ---------------- K1c: gate softmax over nF logits ----------------
__global__ void gatesm_kernel() {
    int b = blockIdx.x;
    int tid = threadIdx.x;    // 256
    int nF = g_nF[b];
    if (nF == 0) return;
    __shared__ float red[256];
    __shared__ float s_logit[MAXF];
    for (int r = tid; r < nF; r += 256) s_logit[r] = g_gate[b][r];
    __syncthreads();
    float m = -1e30f;
    for (int r = tid; r < nF; r += 256) m = fmaxf(m, s_logit[r]);
    red[tid] = m; __syncthreads();
    for (int s = 128; s > 0; s >>= 1) { if (tid < s) red[tid] = fmaxf(red[tid], red[tid + s]); __syncthreads(); }
    float mx = red[0]; __syncthreads();
    float z = 0.f;
    for (int r = tid; r < nF; r += 256) z += expf(s_logit[r] - mx);
    red[tid] = z; __syncthreads();
    for (int s = 128; s > 0; s >>= 1) { if (tid < s) red[tid] += red[tid + s]; __syncthreads(); }
    float Z = red[0];
    for (int r = tid; r < nF; r += 256) g_gate[b][r] = expf(s_logit[r] - mx) / Z;
}

// ---------------- K2a: expand x -> [hi | lo] bf16 ----------------
__global__ void xexp_kernel(const float* __restrict__ x) {
    int row = blockIdx.x;            // b*1024 + l
    const float* src = x + (size_t)row * DD;
    __nv_bfloat16* dst = &g_Xexp[0][0][0] + (size_t)row * KEXP;
    for (int k = threadIdx.x; k < DD; k += 256) {
        float v = src[k];
        __nv_bfloat16 hi = __float2bfloat16(v);
        __nv_bfloat16 lo = __float2bfloat16(v - __bfloat162float(hi));
        dst[k] = hi; dst[DD + k] = lo;
    }
}

// ---------------- K2b: transpose + expand W -> [hi | lo] ----------------
__global__ void wexp_kernel(ProjPtrs pp) {
    int p = blockIdx.z;
    int k0 = blockIdx.y * 32, n0 = blockIdx.x * 32;
    __shared__ float tile[32][33];
    const float* W = pp.W[p];
    int tx = threadIdx.x & 31, ty = threadIdx.x >> 5;   // 32 x 8
    for (int i = ty; i < 32; i += 8) tile[i][tx] = W[(size_t)(k0 + i) * DD + n0 + tx];
    __syncthreads();
    for (int i = ty; i < 32; i += 8) {
        float v = tile[tx][i];   // = W[k0+tx][n0+i]
        __nv_bfloat16 hi = __float2bfloat16(v);
        __nv_bfloat16 lo = __float2bfloat16(v - __bfloat162float(hi));
        __nv_bfloat16* dst = &g_Wexp[p][n0 + i][0];
        dst[k0 + tx] = hi; dst[DD + k0 + tx] = lo;
    }
}

// ---------------- shared GEMM mainloop: 3-term split with fragment reuse ----------------
// smem rows: [hi 32B | lo 32B] per matrix row, stride 80B. One k16-original per iter.
__device__ __forceinline__ void gemm3_loop(const char* aP, const char* bP,
                                           uint32_t sAu, uint32_t sBu, uint32_t stoff,
                                           uint32_t aLd, uint32_t bLd,
                                           float acc[2][8][4]) {
    uint32_t stA = sAu + stoff, stB = sBu + stoff;
    // prologue: chunk 0 -> buffer 0 (each thread: 2x16B of A seg + 2x16B of B seg)
    cp16(stA, aP); cp16(stA + 16, aP + 16);
    cp16(stB, bP); cp16(stB + 16, bP + 16);
    cp_commit();

    for (int it = 0; it < NITER; it++) {
        cp_wait<0>();
        __syncthreads();
        if (it + 1 < NITER) {
            size_t go = (size_t)(it + 1) * 32;
            uint32_t bo = ((it + 1) & 1) * BUFB;
            cp16(stA + bo, aP + go); cp16(stA + bo + 16, aP + go + 16);
            cp16(stB + bo, bP + go); cp16(stB + bo + 16, bP + go + 16);
            cp_commit();
        }
        uint32_t bo = (it & 1) * BUFB;
        uint32_t aB = sAu + bo + aLd;
        uint32_t bB = sBu + bo + bLd;
        uint32_t afh[2][4], afl[2][4];
        ldsm_x4(afh[0], aB);
        ldsm_x4(afh[1], aB + 16 * 80);
        ldsm_x4(afl[0], aB + 32);
        ldsm_x4(afl[1], aB + 16 * 80 + 32);
        #pragma unroll
        for (int j = 0; j < 4; j++) {
            uint32_t rh[4], rl[4];
            ldsm_x4(rh, bB + j * 16 * 80);
            ldsm_x4(rl, bB + j * 16 * 80 + 32);
            uint32_t bh0[2] = {rh[0], rh[1]}, bh1[2] = {rh[2], rh[3]};
            uint32_t bl0[2] = {rl[0], rl[1]}, bl1[2] = {rl[2], rl[3]};
            #pragma unroll
            for (int mt = 0; mt < 2; mt++) {
                mma_bf16(acc[mt][2 * j],     afh[mt], bh0);
                mma_bf16(acc[mt][2 * j],     afh[mt], bl0);
                mma_bf16(acc[mt][2 * j],     afl[mt], bh0);
                mma_bf16(acc[mt][2 * j + 1], afh[mt], bh1);
                mma_bf16(acc[mt][2 * j + 1], afh[mt], bl1);
                mma_bf16(acc[mt][2 * j + 1], afl[mt], bh1);
            }
        }
    }
}

// ---------------- K3: projection GEMMs ----------------
__global__ __launch_bounds__(256, 2) void proj_kernel(ProjPtrs pp) {
    int z = blockIdx.z; int p = z >> 3; int b = z & 7;
    bool isQ = (p < 3);
    int count = isQ ? g_nF[b] : g_nO[b];
    int m0 = blockIdx.y * 128;
    if (count == 0 || m0 >= count) return;
    int n0 = blockIdx.x * 128;   // N=768 -> 6 blocks
    const int* idx = isQ ? g_fIdx[b] : g_oIdx[b];

    __shared__ __align__(16) __nv_bfloat16 sA[2][128 * PADK];
    __shared__ __align__(16) __nv_bfloat16 sB[2][128 * PADK];

    int tid = threadIdx.x, lane = tid & 31, wid = tid >> 5;
    int warp_m = wid & 3, warp_n = wid >> 2;  // 4 x 2 warps -> 32x64 warp tile

    // staging: thread pair per row; shalf selects hi/lo segment
    int srow = tid >> 1, shalf = tid & 1;
    int gm = m0 + srow; if (gm >= count) gm = count - 1;
    const char* aP = (const char*)&g_Xexp[b][0][0] + (size_t)idx[gm] * ROWB + shalf * SEGB;
    const char* bP = (const char*)&g_Wexp[p][0][0] + (size_t)(n0 + srow) * ROWB + shalf * SEGB;
    uint32_t stoff = srow * 80 + shalf * 32;

    int a_row = warp_m * 32 + (lane & 7) + ((lane >> 3) & 1) * 8;
    uint32_t aLd = a_row * 80 + ((lane >> 4) & 1) * 16;
    int b_row = warp_n * 64 + ((lane >> 4) & 1) * 8 + (lane & 7);
    uint32_t bLd = b_row * 80 + ((lane >> 3) & 1) * 16;
    uint32_t sAu = smem_u32(&sA[0][0]);
    uint32_t sBu = smem_u32(&sB[0][0]);

    float acc[2][8][4] = {};
    gemm3_loop(aP, bP, sAu, sBu, stoff, aLd, bLd, acc);

    // epilogue: bias + split to [hi | lo]
    const float* bias = pp.bias[p];
    __nv_bfloat16* outb = isQ ? &g_Qexp[p][b][0][0] : &g_Koexp[p - 3][b][0][0];
    int r0 = lane >> 2, cp = (lane & 3) * 2;
    #pragma unroll
    for (int mt = 0; mt < 2; mt++) {
        #pragma unroll
        for (int c2 = 0; c2 < 2; c2++) {
            int grow = m0 + warp_m * 32 + mt * 16 + r0 + c2 * 8;
            if (grow >= count) continue;
            char* dbase = (char*)(outb + (size_t)grow * KEXP);
            #pragma unroll
            for (int nt = 0; nt < 8; nt++) {
                int n = n0 + warp_n * 64 + nt * 8 + cp;
                float v0 = acc[mt][nt][c2 * 2 + 0] + bias[n];
                float v1 = acc[mt][nt][c2 * 2 + 1] + bias[n + 1];
                float h0 = __bfloat162float(__float2bfloat16(v0));
                float h1 = __bfloat162float(__float2bfloat16(v1));
                *(uint32_t*)(dbase + 2 * n) = packbf(v0, v1);
                *(uint32_t*)(dbase + 2 * (DD + n)) = packbf(v0 - h0, v1 - h1);
            }
        }
    }
}

// ---------------- K4: score GEMMs (Q @ Ko^T) ----------------
__global__ __launch_bounds__(256, 2) void score_kernel() {
    int z = blockIdx.z; int t = z >> 3; int b = z & 7;
    int nF = g_nF[b], nO = g_nO[b];
    int l0 = blockIdx.y * 128;
    if (nF == 0 || l0 >= nF) return;
    int m0 = blockIdx.x * 128;
    if (nO == 0 || m0 >= nO) return;

    __shared__ __align__(16) __nv_bfloat16 sA[2][128 * PADK];
    __shared__ __align__(16) __nv_bfloat16 sB[2][128 * PADK];

    int tid = threadIdx.x, lane = tid & 31, wid = tid >> 5;
    int warp_m = wid & 3, warp_n = wid >> 2;

    int srow = tid >> 1, shalf = tid & 1;
    int rA = l0 + srow; if (rA >= nF) rA = nF - 1;
    int rB = m0 + srow; if (rB >= nO) rB = nO - 1;
    const char* aP = (const char*)&g_Qexp[t][b][0][0]  + (size_t)rA * ROWB + shalf * SEGB;
    const char* bP = (const char*)&g_Koexp[t][b][0][0] + (size_t)rB * ROWB + shalf * SEGB;
    uint32_t stoff = srow * 80 + shalf * 32;

    int a_row = warp_m * 32 + (lane & 7) + ((lane >> 3) & 1) * 8;
    uint32_t aLd = a_row * 80 + ((lane >> 4) & 1) * 16;
    int b_row = warp_n * 64 + ((lane >> 4) & 1) * 8 + (lane & 7);
    uint32_t bLd = b_row * 80 + ((lane >> 3) & 1) * 16;
    uint32_t sAu = smem_u32(&sA[0][0]);
    uint32_t sBu = smem_u32(&sB[0][0]);

    float acc[2][8][4] = {};
    gemm3_loop(aP, bP, sAu, sBu, stoff, aLd, bLd, acc);

    float* S = (t == 0) ? &g_Ssup[b][0][0] : (t == 1) ? &g_Scon[b][0][0] : &g_Srep[b][0][0];
    const float scale = 1.0f / sqrtf((float)DD);
    int r0 = lane >> 2, cp = (lane & 3) * 2;
    #pragma unroll
    for (int mt = 0; mt < 2; mt++) {
        #pragma unroll
        for (int c2 = 0; c2 < 2; c2++) {
            int l = l0 + warp_m * 32 + mt * 16 + r0 + c2 * 8;
            if (l >= nF) continue;
            float* Srow = S + (size_t)l * LL;
            #pragma unroll
            for (int nt = 0; nt < 8; nt++) {
                int m = m0 + warp_n * 64 + nt * 8 + cp;
                if (m < nO)     Srow[m]     = acc[mt][nt][c2 * 2 + 0] * scale;
                if (m + 1 < nO) Srow[m + 1] = acc[mt][nt][c2 * 2 + 1] * scale;
            }
        }
    }
}

// ---------------- K5: per-row softmax, write gate-weighted probs in place ----------------
__global__ void softmax_kernel() {
    int b = blockIdx.x;
    int l = blockIdx.y;
    if (l >= g_nF[b]) return;
    int nO = g_nO[b];
    if (nO == 0) return;
    int tid = threadIdx.x;   // 256
    __shared__ float red[256];
    float gate = g_gate[b][l];
    float* Ssup = &g_Ssup[b][l][0];
    float* Srep = &g_Srep[b][l][0];
    const float* Scon = &g_Scon[b][l][0];

    float sv[4], rv[4];
    #pragma unroll
    for (int r = 0; r < 4; r++) {
        int m = tid + r * 256;
        if (m < nO) {
            sv[r] = Ssup[m];
            rv[r] = Srep[m] + tanhf(Scon[m]);
        } else {
            sv[r] = -1e30f;
            rv[r] = -1e30f;
        }
    }
    float mx = fmaxf(fmaxf(sv[0], sv[1]), fmaxf(sv[2], sv[3]));
    red[tid] = mx; __syncthreads();
    for (int s = 128; s > 0; s >>= 1) { if (tid < s) red[tid] = fmaxf(red[tid], red[tid + s]); __syncthreads(); }
    mx = red[0]; __syncthreads();
    float e[4]; float z = 0.f;
    #pragma unroll
    for (int r = 0; r < 4; r++) { e[r] = expf(sv[r] - mx); z += e[r]; }
    red[tid] = z; __syncthreads();
    for (int s = 128; s > 0; s >>= 1) { if (tid < s) red[tid] += red[tid + s]; __syncthreads(); }
    float c = gate / red[0]; __syncthreads();
    #pragma unroll
    for (int r = 0; r < 4; r++) { int m = tid + r * 256; if (m < nO) Ssup[m] = e[r] * c; }
    mx = fmaxf(fmaxf(rv[0], rv[1]), fmaxf(rv[2], rv[3]));
    red[tid] = mx; __syncthreads();
    for (int s = 128; s > 0; s >>= 1) { if (tid < s) red[tid] = fmaxf(red[tid], red[tid + s]); __syncthreads(); }
    mx = red[0]; __syncthreads();
    z = 0.f;
    #pragma unroll
    for (int r = 0; r < 4; r++) { e[r] = expf(rv[r] - mx); z += e[r]; }
    red[tid] = z; __syncthreads();
    for (int s = 128; s > 0; s >>= 1) { if (tid < s) red[tid] += red[tid + s]; __syncthreads(); }
    c = gate / red[0];
    #pragma unroll
    for (int r = 0; r < 4; r++) { int m = tid + r * 256; if (m < nO) Srep[m] = e[r] * c; }
}

// ---------------- K6: column reduction, 8-way row-chunk split + combine ----------------
__global__ void colsum_part() {
    int b = blockIdx.x;
    int m = blockIdx.y * 256 + threadIdx.x;
    int c = blockIdx.z;
    int nF = g_nF[b];
    float a = 0.f, s = 0.f;
    int l0 = c * 64, l1 = min(l0 + 64, nF);
    for (int l = l0; l < l1; l++) {
        a += g_Ssup[b][l][m];
        s += g_Srep[b][l][m];
    }
    g_WsupP[c][b][m] = a;
    g_WrepP[c][b][m] = s;
}
__global__ void colsum_comb() {
    int b = blockIdx.x;
    int m = blockIdx.y * 256 + threadIdx.x;
    if (m >= g_nO[b]) return;
    float a = 0.f, s = 0.f;
    #pragma unroll
    for (int c = 0; c < 8; c++) { a += g_WsupP[c][b][m]; s += g_WrepP[c][b][m]; }
    g_Wsup[b][m] = a;
    g_Wrep[b][m] = s;
}

// ---------------- K7a: fused vectors, 8-way chunk split + combine ----------------
__global__ void fused_part(const float* __restrict__ x) {
    int b = blockIdx.x;
    int sec = blockIdx.y;     // 0=anomaly 1=wrep 2=wsup
    int c = blockIdx.z;
    int tid = threadIdx.x;    // 256, each thread 3 dims
    int nF = g_nF[b], nO = g_nO[b];
    const float* xb = x + (size_t)b * LL * DD;
    float acc[3] = {0.f, 0.f, 0.f};

    if (nF > 0) {
        if (sec == 0) {
            int i0 = c * 64, i1 = min(i0 + 64, nF);
            for (int i = i0; i < i1; i++) {
                float g = g_gate[b][i];
                const float* xr = xb + (size_t)g_fIdx[b][i] * DD;
                #pragma unroll
                for (int r = 0; r < 3; r++) acc[r] += g * xr[tid + r * 256];
            }
        } else if (nO > 0) {
            const float* w = (sec == 1) ? g_Wrep[b] : g_Wsup[b];
            int i0 = c * 128;
            int i1 = min(i0 + 128, nO);
            for (int i = i0; i < i1; i++) {
                float a = w[i];
                const float* xr = xb + (size_t)g_oIdx[b][i] * DD;
                #pragma unroll
                for (int r = 0; r < 3; r++) acc[r] += a * xr[tid + r * 256];
            }
        } else {
            int i0 = c * 128, i1 = i0 + 128;
            for (int i = i0; i < i1; i++) {
                const float* xr = xb + (size_t)i * DD;
                #pragma unroll
                for (int r = 0; r < 3; r++) acc[r] += xr[tid + r * 256] * (1.0f / (float)LL);
            }
        }
    }
    #pragma unroll
    for (int r = 0; r < 3; r++) g_fusedP[b][sec][c][tid + r * 256] = acc[r];
}
__global__ void fused_comb() {
    int b = blockIdx.x;
    int sec = blockIdx.y;
    int tid = threadIdx.x;
    #pragma unroll
    for (int r = 0; r < 3; r++) {
        int d = tid + r * 256;
        float s = 0.f;
        #pragma unroll
        for (int c = 0; c < 8; c++) s += g_fusedP[b][sec][c][d];
        g_fused[b][sec * DD + d] = s;
    }
}

// ---------------- K7b: h1 = relu(fused @ Wf1 + bf1), 4-way k-split ----------------
__global__ void h1_kernel(const float* __restrict__ Wf1, const float* __restrict__ bf1) {
    int b = blockIdx.x;
    int jc = blockIdx.y;     // 12 blocks of 64 outputs
    int tid = threadIdx.x;
    __shared__ float sf[3 * DD];
    __shared__ float red[256];
    for (int i = tid; i < 3 * DD; i += 256) sf[i] = g_fused[b][i];
    __syncthreads();
    int jloc = tid & 63, slice = tid >> 6;
    int j = jc * 64 + jloc;
    float acc = 0.f;
    int i0 = slice * 576;
    #pragma unroll 8
    for (int i = i0; i < i0 + 576; i++) acc += sf[i] * Wf1[(size_t)i * DD + j];
    red[tid] = acc;
    __syncthreads();
    if (tid < 64) {
        float s = red[tid] + red[tid + 64] + red[tid + 128] + red[tid + 192] + bf1[jc * 64 + tid];
        g_h1[b][jc * 64 + tid] = fmaxf(s, 0.0f);
    }
}

// ---------------- K7c: h2 = h1 @ Wf2 + bf2, then layernorm ----------------
__global__ void h2ln_kernel(const float* __restrict__ Wf2, const float* __restrict__ bf2,
                            const float* __restrict__ gamma, const float* __restrict__ beta,
                            float* __restrict__ out) {
    int b = blockIdx.x;
    int tid = threadIdx.x;   // 256, each thread 3 dims
    __shared__ float h1s[DD];
    __shared__ float red[256];
    for (int i = tid; i < DD; i += 256) h1s[i] = g_h1[b][i];
    __syncthreads();

    float h2[3];
    #pragma unroll
    for (int r = 0; r < 3; r++) h2[r] = bf2[tid + r * 256];
    #pragma unroll 8
    for (int i = 0; i < DD; i++) {
        float f = h1s[i];
        #pragma unroll
        for (int r = 0; r < 3; r++) h2[r] += f * Wf2[(size_t)i * DD + tid + r * 256];
    }

    float s = h2[0] + h2[1] + h2[2];
    red[tid] = s; __syncthreads();
    for (int st = 128; st > 0; st >>= 1) { if (tid < st) red[tid] += red[tid + st]; __syncthreads(); }
    float mu = red[0] / (float)DD;
    __syncthreads();
    float v = 0.f;
    #pragma unroll
    for (int r = 0; r < 3; r++) { float dlt = h2[r] - mu; v += dlt * dlt; }
    red[tid] = v; __syncthreads();
    for (int st = 128; st > 0; st >>= 1) { if (tid < st) red[tid] += red[tid + st]; __syncthreads(); }
    float inv = rsqrtf(red[0] / (float)DD + 1e-5f);
    #pragma unroll
    for (int r = 0; r < 3; r++) {
        int j = tid + r * 256;
        out[(size_t)b * DD + j] = (h2[r] - mu) * inv * gamma[j] + beta[j];
    }
}

// ---------------- launch ----------------
extern "C" void kernel_launch(void* const* d_in, const int* in_sizes, int n_in,
                              void* d_out, int out_size) {
    (void)in_sizes; (void)n_in; (void)out_size;
    const float* x     = (const float*)d_in[0];
    const int*   x_ids = (const int*)d_in[1];
    const int*   pad   = (const int*)d_in[2];
    const float* Wa    = (const float*)d_in[3];
    const float* ba    = (const float*)d_in[4];

    ProjPtrs pp;
    pp.W[0] = (const float*)d_in[5];  pp.bias[0] = (const float*)d_in[6];   // qs
    pp.W[1] = (const float*)d_in[9];  pp.bias[1] = (const float*)d_in[10];  // qc
    pp.W[2] = (const float*)d_in[13]; pp.bias[2] = (const float*)d_in[14];  // qr
    pp.W[3] = (const float*)d_in[7];  pp.bias[3] = (const float*)d_in[8];   // ks
    pp.W[4] = (const float*)d_in[11]; pp.bias[4] = (const float*)d_in[12];  // kc
    pp.W[5] = (const float*)d_in[15]; pp.bias[5] = (const float*)d_in[16];  // kr

    mask_kernel<<<BB, 256>>>(x_ids, pad);
    logit_kernel<<<dim3(BB, 2), 256>>>(x, Wa, ba);
    gatesm_kernel<<<BB, 256>>>();
    xexp_kernel<<<BB * LL, 256>>>(x);
    wexp_kernel<<<dim3(24, 24, 6), 256>>>(pp);
    proj_kernel<<<dim3(6, 8, 48), 256>>>(pp);
    score_kernel<<<dim3(8, 4, 24), 256>>>();
    softmax_kernel<<<dim3(BB, MAXF), 256>>>();
    colsum_part<<<dim3(BB, LL / 256, 8), 256>>>();
    colsum_comb<<<dim3(BB, LL / 256), 256>>>();
    fused_part<<<dim3(BB, 3, 8), 256>>>(x);
    fused_comb<<<dim3(BB, 3), 256>>>();
    h1_kernel<<<dim3(BB, 12), 256>>>((const float*)d_in[17], (const float*)d_in[18]);
    h2ln_kernel<<<BB, 256>>>((const float*)d_in[19], (const float*)d_in[20],
                             (const float*)d_in[21], (const float*)d_in[22],
                             (float*)d_out);
}

// round 13
// speedup vs baseline: 1.4658x; 1.4658x over previous
#include <cuda_runtime.h>
#include <cuda_bf16.h>
#include <math.h>
#include <stdint.h>
#include <string.h>

#define BB 8
#define LL 1024
#define DD 768
#define MAXF 512   // nF <= 512
#define KEXP 1536  // [hi | lo] split-bf16 storage (2*DD)
#define ROWB 3072  // bytes per row (KEXP * 2)
#define SEGB 1536  // bytes per segment (DD * 2)
#define NITER 48   // 768 / 16 original-K per iter
#define PADK 40    // smem row stride in bf16 (80 bytes)
#define BUFB (128 * PADK * 2)  // bytes per smem buffer (10240)

// ---------------- scratch (device statics; no allocation) ----------------
__device__ int   g_nF[BB], g_nO[BB];
__device__ int   g_fIdx[BB][MAXF];
__device__ int   g_oIdx[BB][LL];
__device__ float g_gate[BB][MAXF];
__device__ __nv_bfloat16 g_Xexp[BB][LL][KEXP];        // [hi | lo]
__device__ __nv_bfloat16 g_Wexp[6][DD][KEXP];         // W^T rows, [hi | lo]
__device__ __nv_bfloat16 g_Qexp[3][BB][MAXF][KEXP];   // [hi | lo]
__device__ __nv_bfloat16 g_Koexp[3][BB][LL][KEXP];    // [hi | lo]
__device__ float g_Ssup[BB][MAXF][LL];
__device__ float g_Scon[BB][MAXF][LL];
__device__ float g_Srep[BB][MAXF][LL];
__device__ float g_Wsup[BB][LL];
__device__ float g_Wrep[BB][LL];
__device__ float g_WsupP[8][BB][LL];
__device__ float g_WrepP[8][BB][LL];
__device__ float g_fusedP[BB][3][8][DD];
__device__ float g_fused[BB][3 * DD];
__device__ float g_h1[BB][DD];

struct ProjPtrs { const float* W[6]; const float* bias[6]; };

// ---------------- helpers ----------------
__device__ __forceinline__ uint32_t smem_u32(const void* p) {
    return (uint32_t)__cvta_generic_to_shared(p);
}
__device__ __forceinline__ void ldsm_x4(uint32_t r[4], uint32_t addr) {
    asm volatile("ldmatrix.sync.aligned.m8n8.x4.shared.b16 {%0,%1,%2,%3}, [%4];"
                 : "=r"(r[0]), "=r"(r[1]), "=r"(r[2]), "=r"(r[3]) : "r"(addr));
}
__device__ __forceinline__ void mma_bf16(float c[4], const uint32_t a[4], const uint32_t b[2]) {
    asm volatile("mma.sync.aligned.m16n8k16.row.col.f32.bf16.bf16.f32 "
                 "{%0,%1,%2,%3}, {%4,%5,%6,%7}, {%8,%9}, {%0,%1,%2,%3};"
                 : "+f"(c[0]), "+f"(c[1]), "+f"(c[2]), "+f"(c[3])
                 : "r"(a[0]), "r"(a[1]), "r"(a[2]), "r"(a[3]), "r"(b[0]), "r"(b[1]));
}
__device__ __forceinline__ uint32_t packbf(float v0, float v1) {
    __nv_bfloat162 t = __floats2bfloat162_rn(v0, v1);
    uint32_t u;
    memcpy(&u, &t, 4);
    return u;
}
__device__ __forceinline__ void cp16(uint32_t dst, const void* src) {
    asm volatile("cp.async.cg.shared.global [%0], [%1], 16;" :: "r"(dst), "l"(src));
}
__device__ __forceinline__ void cp_commit() {
    asm volatile("cp.async.commit_group;" ::: "memory");
}
template <int N>
__device__ __forceinline__ void cp_wait() {
    asm volatile("cp.async.wait_group %0;" :: "n"(N) : "memory");
}

// ---------------- K1a: masks + compaction ----------------
__global__ void mask_kernel(const int* __restrict__ x_ids,
                            const int* __restrict__ pad_p) {
    int b = blockIdx.x;
    int tid = threadIdx.x;           // 256 threads
    __shared__ unsigned char s_valid[LL];
    __shared__ int s_ired[256];
    int pad = *pad_p;
    int cnt = 0;
    for (int i = tid; i < LL; i += 256) {
        int v = (x_ids[b * LL + i] != pad) ? 1 : 0;
        s_valid[i] = (unsigned char)v;
        cnt += v;
    }
    s_ired[tid] = cnt;
    __syncthreads();
    for (int s = 128; s > 0; s >>= 1) {
        if (tid < s) s_ired[tid] += s_ired[tid + s];
        __syncthreads();
    }
    int vl = s_ired[0];
    int sep = vl / 2;
    if (sep < 1) sep = 1;
    if (sep > LL - 2) sep = LL - 2;
    if (tid == 0) {
        int nf = 0, no = 0;
        for (int i = 0; i < LL; i++) {
            if (s_valid[i]) {
                if (i < sep)      g_fIdx[b][nf++] = i;
                else if (i > sep) g_oIdx[b][no++] = i;
            }
        }
        g_nF[b] = nf;
        g_nO[b] = no;
    }
}

// ---------------- K1b: anomaly logits (raw, into g_gate) ----------------
__global__ void logit_kernel(const float* __restrict__ x,
                             const float* __restrict__ Wa,
                             const float* __restrict__ ba) {
    int b = blockIdx.x;
    int r = blockIdx.y * 256 + threadIdx.x;
    __shared__ float s_Wa[DD];
    for (int i = threadIdx.x; i < DD; i += 256) s_Wa[i] = Wa[i];
    __syncthreads();
    if (r >= g_nF[b]) return;
    const float* xr = x + ((size_t)b * LL + g_fIdx[b][r]) * DD;
    float acc = ba[0];
    #pragma unroll 8
    for (int k = 0; k < DD; k++) acc += xr[k] * s_Wa[k];
    g_gate[b][r] = acc;
}

// ---------------- K1c: gate softmax over nF logits ----------------
__global__ void gatesm_kernel() {
    int b = blockIdx.x;
    int tid = threadIdx.x;    // 256
    int nF = g_nF[b];
    if (nF == 0) return;
    __shared__ float red[256];
    __shared__ float s_logit[MAXF];
    for (int r = tid; r < nF; r += 256) s_logit[r] = g_gate[b][r];
    __syncthreads();
    float m = -1e30f;
    for (int r = tid; r < nF; r += 256) m = fmaxf(m, s_logit[r]);
    red[tid] = m; __syncthreads();
    for (int s = 128; s > 0; s >>= 1) { if (tid < s) red[tid] = fmaxf(red[tid], red[tid + s]); __syncthreads(); }
    float mx = red[0]; __syncthreads();
    float z = 0.f;
    for (int r = tid; r < nF; r += 256) z += expf(s_logit[r] - mx);
    red[tid] = z; __syncthreads();
    for (int s = 128; s > 0; s >>= 1) { if (tid < s) red[tid] += red[tid + s]; __syncthreads(); }
    float Z = red[0];
    for (int r = tid; r < nF; r += 256) g_gate[b][r] = expf(s_logit[r] - mx) / Z;
}

// ---------------- K2a: expand x -> [hi | lo] bf16 ----------------
__global__ void xexp_kernel(const float* __restrict__ x) {
    int row = blockIdx.x;            // b*1024 + l
    const float* src = x + (size_t)row * DD;
    __nv_bfloat16* dst = &g_Xexp[0][0][0] + (size_t)row * KEXP;
    for (int k = threadIdx.x; k < DD; k += 256) {
        float v = src[k];
        __nv_bfloat16 hi = __float2bfloat16(v);
        __nv_bfloat16 lo = __float2bfloat16(v - __bfloat162float(hi));
        dst[k] = hi; dst[DD + k] = lo;
    }
}

// ---------------- K2b: transpose + expand W -> [hi | lo] ----------------
__global__ void wexp_kernel(ProjPtrs pp) {
    int p = blockIdx.z;
    int k0 = blockIdx.y * 32, n0 = blockIdx.x * 32;
    __shared__ float tile[32][33];
    const float* W = pp.W[p];
    int tx = threadIdx.x & 31, ty = threadIdx.x >> 5;   // 32 x 8
    for (int i = ty; i < 32; i += 8) tile[i][tx] = W[(size_t)(k0 + i) * DD + n0 + tx];
    __syncthreads();
    for (int i = ty; i < 32; i += 8) {
        float v = tile[tx][i];   // = W[k0+tx][n0+i]
        __nv_bfloat16 hi = __float2bfloat16(v);
        __nv_bfloat16 lo = __float2bfloat16(v - __bfloat162float(hi));
        __nv_bfloat16* dst = &g_Wexp[p][n0 + i][0];
        dst[k0 + tx] = hi; dst[DD + k0 + tx] = lo;
    }
}

// ---------------- shared GEMM mainloop: 3-term split, term-major issue ----------------
// smem rows: [hi 32B | lo 32B] per matrix row, stride 80B. One original k16 per iter.
// Term-major order inside each j-block: same-acc reuse distance = 4 MMAs.
__device__ __forceinline__ void gemm3_loop(const char* aP, const char* bP,
                                           uint32_t sAu, uint32_t sBu, uint32_t stoff,
                                           uint32_t aLd, uint32_t bLd,
                                           float acc[2][8][4]) {
    uint32_t stA = sAu + stoff, stB = sBu + stoff;
    cp16(stA, aP); cp16(stA + 16, aP + 16);
    cp16(stB, bP); cp16(stB + 16, bP + 16);
    cp_commit();

    for (int it = 0; it < NITER; it++) {
        cp_wait<0>();
        __syncthreads();
        if (it + 1 < NITER) {
            size_t go = (size_t)(it + 1) * 32;
            uint32_t bo = ((it + 1) & 1) * BUFB;
            cp16(stA + bo, aP + go); cp16(stA + bo + 16, aP + go + 16);
            cp16(stB + bo, bP + go); cp16(stB + bo + 16, bP + go + 16);
            cp_commit();
        }
        uint32_t bo = (it & 1) * BUFB;
        uint32_t aB = sAu + bo + aLd;
        uint32_t bB = sBu + bo + bLd;
        uint32_t afh[2][4], afl[2][4];
        ldsm_x4(afh[0], aB);
        ldsm_x4(afh[1], aB + 16 * 80);
        ldsm_x4(afl[0], aB + 32);
        ldsm_x4(afl[1], aB + 16 * 80 + 32);
        #pragma unroll
        for (int j = 0; j < 4; j++) {
            uint32_t rh[4], rl[4];
            ldsm_x4(rh, bB + j * 16 * 80);
            ldsm_x4(rl, bB + j * 16 * 80 + 32);
            uint32_t bh0[2] = {rh[0], rh[1]}, bh1[2] = {rh[2], rh[3]};
            uint32_t bl0[2] = {rl[0], rl[1]}, bl1[2] = {rl[2], rl[3]};
            // term-major: all 4 accs get hh, then hl, then lh (reuse distance 4)
            mma_bf16(acc[0][2 * j],     afh[0], bh0);
            mma_bf16(acc[0][2 * j + 1], afh[0], bh1);
            mma_bf16(acc[1][2 * j],     afh[1], bh0);
            mma_bf16(acc[1][2 * j + 1], afh[1], bh1);
            mma_bf16(acc[0][2 * j],     afh[0], bl0);
            mma_bf16(acc[0][2 * j + 1], afh[0], bl1);
            mma_bf16(acc[1][2 * j],     afh[1], bl0);
            mma_bf16(acc[1][2 * j + 1], afh[1], bl1);
            mma_bf16(acc[0][2 * j],     afl[0], bh0);
            mma_bf16(acc[0][2 * j + 1], afl[0], bh1);
            mma_bf16(acc[1][2 * j],     afl[1], bh0);
            mma_bf16(acc[1][2 * j + 1], afl[1], bh1);
        }
    }
}

// ---------------- K3: projection GEMMs ----------------
__global__ __launch_bounds__(256, 2) void proj_kernel(ProjPtrs pp) {
    int z = blockIdx.z; int p = z >> 3; int b = z & 7;
    bool isQ = (p < 3);
    int count = isQ ? g_nF[b] : g_nO[b];
    int m0 = blockIdx.y * 128;
    if (count == 0 || m0 >= count) return;
    int n0 = blockIdx.x * 128;   // N=768 -> 6 blocks
    const int* idx = isQ ? g_fIdx[b] : g_oIdx[b];

    __shared__ __align__(16) __nv_bfloat16 sA[2][128 * PADK];
    __shared__ __align__(16) __nv_bfloat16 sB[2][128 * PADK];

    int tid = threadIdx.x, lane = tid & 31, wid = tid >> 5;
    int warp_m = wid & 3, warp_n = wid >> 2;  // 4 x 2 warps -> 32x64 warp tile

    int srow = tid >> 1, shalf = tid & 1;
    int gm = m0 + srow; if (gm >= count) gm = count - 1;
    const char* aP = (const char*)&g_Xexp[b][0][0] + (size_t)idx[gm] * ROWB + shalf * SEGB;
    const char* bP = (const char*)&g_Wexp[p][0][0] + (size_t)(n0 + srow) * ROWB + shalf * SEGB;
    uint32_t stoff = srow * 80 + shalf * 32;

    int a_row = warp_m * 32 + (lane & 7) + ((lane >> 3) & 1) * 8;
    uint32_t aLd = a_row * 80 + ((lane >> 4) & 1) * 16;
    int b_row = warp_n * 64 + ((lane >> 4) & 1) * 8 + (lane & 7);
    uint32_t bLd = b_row * 80 + ((lane >> 3) & 1) * 16;
    uint32_t sAu = smem_u32(&sA[0][0]);
    uint32_t sBu = smem_u32(&sB[0][0]);

    float acc[2][8][4] = {};
    gemm3_loop(aP, bP, sAu, sBu, stoff, aLd, bLd, acc);

    // epilogue: bias + split to [hi | lo]
    const float* bias = pp.bias[p];
    __nv_bfloat16* outb = isQ ? &g_Qexp[p][b][0][0] : &g_Koexp[p - 3][b][0][0];
    int r0 = lane >> 2, cp = (lane & 3) * 2;
    #pragma unroll
    for (int mt = 0; mt < 2; mt++) {
        #pragma unroll
        for (int c2 = 0; c2 < 2; c2++) {
            int grow = m0 + warp_m * 32 + mt * 16 + r0 + c2 * 8;
            if (grow >= count) continue;
            char* dbase = (char*)(outb + (size_t)grow * KEXP);
            #pragma unroll
            for (int nt = 0; nt < 8; nt++) {
                int n = n0 + warp_n * 64 + nt * 8 + cp;
                float v0 = acc[mt][nt][c2 * 2 + 0] + bias[n];
                float v1 = acc[mt][nt][c2 * 2 + 1] + bias[n + 1];
                float h0 = __bfloat162float(__float2bfloat16(v0));
                float h1 = __bfloat162float(__float2bfloat16(v1));
                *(uint32_t*)(dbase + 2 * n) = packbf(v0, v1);
                *(uint32_t*)(dbase + 2 * (DD + n)) = packbf(v0 - h0, v1 - h1);
            }
        }
    }
}

// ---------------- K4: score GEMMs (Q @ Ko^T) ----------------
__global__ __launch_bounds__(256, 2) void score_kernel() {
    int z = blockIdx.z; int t = z >> 3; int b = z & 7;
    int nF = g_nF[b], nO = g_nO[b];
    int l0 = blockIdx.y * 128;
    if (nF == 0 || l0 >= nF) return;
    int m0 = blockIdx.x * 128;
    if (nO == 0 || m0 >= nO) return;

    __shared__ __align__(16) __nv_bfloat16 sA[2][128 * PADK];
    __shared__ __align__(16) __nv_bfloat16 sB[2][128 * PADK];

    int tid = threadIdx.x, lane = tid & 31, wid = tid >> 5;
    int warp_m = wid & 3, warp_n = wid >> 2;

    int srow = tid >> 1, shalf = tid & 1;
    int rA = l0 + srow; if (rA >= nF) rA = nF - 1;
    int rB = m0 + srow; if (rB >= nO) rB = nO - 1;
    const char* aP = (const char*)&g_Qexp[t][b][0][0]  + (size_t)rA * ROWB + shalf * SEGB;
    const char* bP = (const char*)&g_Koexp[t][b][0][0] + (size_t)rB * ROWB + shalf * SEGB;
    uint32_t stoff = srow * 80 + shalf * 32;

    int a_row = warp_m * 32 + (lane & 7) + ((lane >> 3) & 1) * 8;
    uint32_t aLd = a_row * 80 + ((lane >> 4) & 1) * 16;
    int b_row = warp_n * 64 + ((lane >> 4) & 1) * 8 + (lane & 7);
    uint32_t bLd = b_row * 80 + ((lane >> 3) & 1) * 16;
    uint32_t sAu = smem_u32(&sA[0][0]);
    uint32_t sBu = smem_u32(&sB[0][0]);

    float acc[2][8][4] = {};
    gemm3_loop(aP, bP, sAu, sBu, stoff, aLd, bLd, acc);

    float* S = (t == 0) ? &g_Ssup[b][0][0] : (t == 1) ? &g_Scon[b][0][0] : &g_Srep[b][0][0];
    const float scale = 1.0f / sqrtf((float)DD);
    int r0 = lane >> 2, cp = (lane & 3) * 2;
    #pragma unroll
    for (int mt = 0; mt < 2; mt++) {
        #pragma unroll
        for (int c2 = 0; c2 < 2; c2++) {
            int l = l0 + warp_m * 32 + mt * 16 + r0 + c2 * 8;
            if (l >= nF) continue;
            float* Srow = S + (size_t)l * LL;
            #pragma unroll
            for (int nt = 0; nt < 8; nt++) {
                int m = m0 + warp_n * 64 + nt * 8 + cp;
                if (m < nO)     Srow[m]     = acc[mt][nt][c2 * 2 + 0] * scale;
                if (m + 1 < nO) Srow[m + 1] = acc[mt][nt][c2 * 2 + 1] * scale;
            }
        }
    }
}

// ---------------- K5: per-row softmax, write gate-weighted probs in place ----------------
__global__ void softmax_kernel() {
    int b = blockIdx.x;
    int l = blockIdx.y;
    if (l >= g_nF[b]) return;
    int nO = g_nO[b];
    if (nO == 0) return;
    int tid = threadIdx.x;   // 256
    __shared__ float red[256];
    float gate = g_gate[b][l];
    float* Ssup = &g_Ssup[b][l][0];
    float* Srep = &g_Srep[b][l][0];
    const float* Scon = &g_Scon[b][l][0];

    float sv[4], rv[4];
    #pragma unroll
    for (int r = 0; r < 4; r++) {
        int m = tid + r * 256;
        if (m < nO) {
            sv[r] = Ssup[m];
            rv[r] = Srep[m] + tanhf(Scon[m]);
        } else {
            sv[r] = -1e30f;
            rv[r] = -1e30f;
        }
    }
    float mx = fmaxf(fmaxf(sv[0], sv[1]), fmaxf(sv[2], sv[3]));
    red[tid] = mx; __syncthreads();
    for (int s = 128; s > 0; s >>= 1) { if (tid < s) red[tid] = fmaxf(red[tid], red[tid + s]); __syncthreads(); }
    mx = red[0]; __syncthreads();
    float e[4]; float z = 0.f;
    #pragma unroll
    for (int r = 0; r < 4; r++) { e[r] = expf(sv[r] - mx); z += e[r]; }
    red[tid] = z; __syncthreads();
    for (int s = 128; s > 0; s >>= 1) { if (tid < s) red[tid] += red[tid + s]; __syncthreads(); }
    float c = gate / red[0]; __syncthreads();
    #pragma unroll
    for (int r = 0; r < 4; r++) { int m = tid + r * 256; if (m < nO) Ssup[m] = e[r] * c; }
    mx = fmaxf(fmaxf(rv[0], rv[1]), fmaxf(rv[2], rv[3]));
    red[tid] = mx; __syncthreads();
    for (int s = 128; s > 0; s >>= 1) { if (tid < s) red[tid] = fmaxf(red[tid], red[tid + s]); __syncthreads(); }
    mx = red[0]; __syncthreads();
    z = 0.f;
    #pragma unroll
    for (int r = 0; r < 4; r++) { e[r] = expf(rv[r] - mx); z += e[r]; }
    red[tid] = z; __syncthreads();
    for (int s = 128; s > 0; s >>= 1) { if (tid < s) red[tid] += red[tid + s]; __syncthreads(); }
    c = gate / red[0];
    #pragma unroll
    for (int r = 0; r < 4; r++) { int m = tid + r * 256; if (m < nO) Srep[m] = e[r] * c; }
}

// ---------------- K6: column reduction, 8-way row-chunk split + combine ----------------
__global__ void colsum_part() {
    int b = blockIdx.x;
    int m = blockIdx.y * 256 + threadIdx.x;
    int c = blockIdx.z;
    int nF = g_nF[b];
    float a = 0.f, s = 0.f;
    int l0 = c * 64, l1 = min(l0 + 64, nF);
    for (int l = l0; l < l1; l++) {
        a += g_Ssup[b][l][m];
        s += g_Srep[b][l][m];
    }
    g_WsupP[c][b][m] = a;
    g_WrepP[c][b][m] = s;
}
__global__ void colsum_comb() {
    int b = blockIdx.x;
    int m = blockIdx.y * 256 + threadIdx.x;
    if (m >= g_nO[b]) return;
    float a = 0.f, s = 0.f;
    #pragma unroll
    for (int c = 0; c < 8; c++) { a += g_WsupP[c][b][m]; s += g_WrepP[c][b][m]; }
    g_Wsup[b][m] = a;
    g_Wrep[b][m] = s;
}

// ---------------- K7a: fused vectors, 8-way chunk split + combine ----------------
__global__ void fused_part(const float* __restrict__ x) {
    int b = blockIdx.x;
    int sec = blockIdx.y;     // 0=anomaly 1=wrep 2=wsup
    int c = blockIdx.z;
    int tid = threadIdx.x;    // 256, each thread 3 dims
    int nF = g_nF[b], nO = g_nO[b];
    const float* xb = x + (size_t)b * LL * DD;
    float acc[3] = {0.f, 0.f, 0.f};

    if (nF > 0) {
        if (sec == 0) {
            int i0 = c * 64, i1 = min(i0 + 64, nF);
            for (int i = i0; i < i1; i++) {
                float g = g_gate[b][i];
                const float* xr = xb + (size_t)g_fIdx[b][i] * DD;
                #pragma unroll
                for (int r = 0; r < 3; r++) acc[r] += g * xr[tid + r * 256];
            }
        } else if (nO > 0) {
            const float* w = (sec == 1) ? g_Wrep[b] : g_Wsup[b];
            int i0 = c * 128;
            int i1 = min(i0 + 128, nO);
            for (int i = i0; i < i1; i++) {
                float a = w[i];
                const float* xr = xb + (size_t)g_oIdx[b][i] * DD;
                #pragma unroll
                for (int r = 0; r < 3; r++) acc[r] += a * xr[tid + r * 256];
            }
        } else {
            int i0 = c * 128, i1 = i0 + 128;
            for (int i = i0; i < i1; i++) {
                const float* xr = xb + (size_t)i * DD;
                #pragma unroll
                for (int r = 0; r < 3; r++) acc[r] += xr[tid + r * 256] * (1.0f / (float)LL);
            }
        }
    }
    #pragma unroll
    for (int r = 0; r < 3; r++) g_fusedP[b][sec][c][tid + r * 256] = acc[r];
}
__global__ void fused_comb() {
    int b = blockIdx.x;
    int sec = blockIdx.y;
    int tid = threadIdx.x;
    #pragma unroll
    for (int r = 0; r < 3; r++) {
        int d = tid + r * 256;
        float s = 0.f;
        #pragma unroll
        for (int c = 0; c < 8; c++) s += g_fusedP[b][sec][c][d];
        g_fused[b][sec * DD + d] = s;
    }
}

// ---------------- K7b: h1 = relu(fused @ Wf1 + bf1), 4-way k-split ----------------
__global__ void h1_kernel(const float* __restrict__ Wf1, const float* __restrict__ bf1) {
    int b = blockIdx.x;
    int jc = blockIdx.y;     // 12 blocks of 64 outputs
    int tid = threadIdx.x;
    __shared__ float sf[3 * DD];
    __shared__ float red[256];
    for (int i = tid; i < 3 * DD; i += 256) sf[i] = g_fused[b][i];
    __syncthreads();
    int jloc = tid & 63, slice = tid >> 6;
    int j = jc * 64 + jloc;
    float acc = 0.f;
    int i0 = slice * 576;
    #pragma unroll 8
    for (int i = i0; i < i0 + 576; i++) acc += sf[i] * Wf1[(size_t)i * DD + j];
    red[tid] = acc;
    __syncthreads();
    if (tid < 64) {
        float s = red[tid] + red[tid + 64] + red[tid + 128] + red[tid + 192] + bf1[jc * 64 + tid];
        g_h1[b][jc * 64 + tid] = fmaxf(s, 0.0f);
    }
}

// ---------------- K7c: h2 = h1 @ Wf2 + bf2, then layernorm ----------------
__global__ void h2ln_kernel(const float* __restrict__ Wf2, const float* __restrict__ bf2,
                            const float* __restrict__ gamma, const float* __restrict__ beta,
                            float* __restrict__ out) {
    int b = blockIdx.x;
    int tid = threadIdx.x;   // 256, each thread 3 dims
    __shared__ float h1s[DD];
    __shared__ float red[256];
    for (int i = tid; i < DD; i += 256) h1s[i] = g_h1[b][i];
    __syncthreads();

    float h2[3];
    #pragma unroll
    for (int r = 0; r < 3; r++) h2[r] = bf2[tid + r * 256];
    #pragma unroll 8
    for (int i = 0; i < DD; i++) {
        float f = h1s[i];
        #pragma unroll
        for (int r = 0; r < 3; r++) h2[r] += f * Wf2[(size_t)i * DD + tid + r * 256];
    }

    float s = h2[0] + h2[1] + h2[2];
    red[tid] = s; __syncthreads();
    for (int st = 128; st > 0; st >>= 1) { if (tid < st) red[tid] += red[tid + st]; __syncthreads(); }
    float mu = red[0] / (float)DD;
    __syncthreads();
    float v = 0.f;
    #pragma unroll
    for (int r = 0; r < 3; r++) { float dlt = h2[r] - mu; v += dlt * dlt; }
    red[tid] = v; __syncthreads();
    for (int st = 128; st > 0; st >>= 1) { if (tid < st) red[tid] += red[tid + st]; __syncthreads(); }
    float inv = rsqrtf(red[0] / (float)DD + 1e-5f);
    #pragma unroll
    for (int r = 0; r < 3; r++) {
        int j = tid + r * 256;
        out[(size_t)b * DD + j] = (h2[r] - mu) * inv * gamma[j] + beta[j];
    }
}

// ---------------- launch ----------------
extern "C" void kernel_launch(void* const* d_in, const int* in_sizes, int n_in,
                              void* d_out, int out_size) {
    (void)in_sizes; (void)n_in; (void)out_size;
    const float* x     = (const float*)d_in[0];
    const int*   x_ids = (const int*)d_in[1];
    const int*   pad   = (const int*)d_in[2];
    const float* Wa    = (const float*)d_in[3];
    const float* ba    = (const float*)d_in[4];

    ProjPtrs pp;
    pp.W[0] = (const float*)d_in[5];  pp.bias[0] = (const float*)d_in[6];   // qs
    pp.W[1] = (const float*)d_in[9];  pp.bias[1] = (const float*)d_in[10];  // qc
    pp.W[2] = (const float*)d_in[13]; pp.bias[2] = (const float*)d_in[14];  // qr
    pp.W[3] = (const float*)d_in[7];  pp.bias[3] = (const float*)d_in[8];   // ks
    pp.W[4] = (const float*)d_in[11]; pp.bias[4] = (const float*)d_in[12];  // kc
    pp.W[5] = (const float*)d_in[15]; pp.bias[5] = (const float*)d_in[16];  // kr

    mask_kernel<<<BB, 256>>>(x_ids, pad);
    logit_kernel<<<dim3(BB, 2), 256>>>(x, Wa, ba);
    gatesm_kernel<<<BB, 256>>>();
    xexp_kernel<<<BB * LL, 256>>>(x);
    wexp_kernel<<<dim3(24, 24, 6), 256>>>(pp);
    proj_kernel<<<dim3(6, 8, 48), 256>>>(pp);
    score_kernel<<<dim3(8, 4, 24), 256>>>();
    softmax_kernel<<<dim3(BB, MAXF), 256>>>();
    colsum_part<<<dim3(BB, LL / 256, 8), 256>>>();
    colsum_comb<<<dim3(BB, LL / 256), 256>>>();
    fused_part<<<dim3(BB, 3, 8), 256>>>(x);
    fused_comb<<<dim3(BB, 3), 256>>>();
    h1_kernel<<<dim3(BB, 12), 256>>>((const float*)d_in[17], (const float*)d_in[18]);
    h2ln_kernel<<<BB, 256>>>((const float*)d_in[19], (const float*)d_in[20],
                             (const float*)d_in[21], (const float*)d_in[22],
                             (float*)d_out);
}

// round 15
// speedup vs baseline: 1.5086x; 1.0292x over previous
#include <cuda_runtime.h>
#include <cuda_bf16.h>
#include <math.h>
#include <stdint.h>
#include <string.h>

#define BB 8
#define LL 1024
#define DD 768
#define MAXF 512   // nF <= 512
#define KEXP 1536  // [hi | lo] split-bf16 storage (2*DD)
#define ROWB 3072  // bytes per row (KEXP * 2)
#define SEGB 1536  // bytes per segment (DD * 2)
#define NITER 48   // one original k16 per iter
#define SBUF 8192  // bytes per smem stage buffer (128 rows x 64B, swizzled)
#define BOFF (3 * SBUF)   // B region offset inside combined smem block

// ---------------- scratch (device statics; no allocation) ----------------
__device__ int   g_nF[BB], g_nO[BB];
__device__ int   g_fIdx[BB][MAXF];
__device__ int   g_oIdx[BB][LL];
__device__ float g_gate[BB][MAXF];
__device__ __nv_bfloat16 g_Xexp[BB][LL][KEXP];        // [hi | lo]
__device__ __nv_bfloat16 g_Wexp[6][DD][KEXP];         // W^T rows, [hi | lo]
__device__ __nv_bfloat16 g_Qexp[3][BB][MAXF][KEXP];   // [hi | lo]
__device__ __nv_bfloat16 g_Koexp[3][BB][LL][KEXP];    // [hi | lo]
__device__ float g_Ssup[BB][MAXF][LL];
__device__ float g_Scon[BB][MAXF][LL];
__device__ float g_Srep[BB][MAXF][LL];
__device__ float g_Wsup[BB][LL];
__device__ float g_Wrep[BB][LL];
__device__ float g_WsupP[8][BB][LL];
__device__ float g_WrepP[8][BB][LL];
__device__ float g_fusedP[BB][3][8][DD];
__device__ float g_fused[BB][3 * DD];
__device__ float g_h1[BB][DD];

struct ProjPtrs { const float* W[6]; const float* bias[6]; };

// ---------------- helpers ----------------
__device__ __forceinline__ uint32_t smem_u32(const void* p) {
    return (uint32_t)__cvta_generic_to_shared(p);
}
__device__ __forceinline__ void ldsm_x4(uint32_t r[4], uint32_t addr) {
    asm volatile("ldmatrix.sync.aligned.m8n8.x4.shared.b16 {%0,%1,%2,%3}, [%4];"
                 : "=r"(r[0]), "=r"(r[1]), "=r"(r[2]), "=r"(r[3]) : "r"(addr));
}
__device__ __forceinline__ void mma_bf16(float c[4], const uint32_t a[4], const uint32_t b[2]) {
    asm volatile("mma.sync.aligned.m16n8k16.row.col.f32.bf16.bf16.f32 "
                 "{%0,%1,%2,%3}, {%4,%5,%6,%7}, {%8,%9}, {%0,%1,%2,%3};"
                 : "+f"(c[0]), "+f"(c[1]), "+f"(c[2]), "+f"(c[3])
                 : "r"(a[0]), "r"(a[1]), "r"(a[2]), "r"(a[3]), "r"(b[0]), "r"(b[1]));
}
__device__ __forceinline__ uint32_t packbf(float v0, float v1) {
    __nv_bfloat162 t = __floats2bfloat162_rn(v0, v1);
    uint32_t u;
    memcpy(&u, &t, 4);
    return u;
}
__device__ __forceinline__ void cp16(uint32_t dst, const void* src) {
    asm volatile("cp.async.cg.shared.global [%0], [%1], 16;" :: "r"(dst), "l"(src));
}
__device__ __forceinline__ void cp_commit() {
    asm volatile("cp.async.commit_group;" ::: "memory");
}
template <int N>
__device__ __forceinline__ void cp_wait() {
    asm volatile("cp.async.wait_group %0;" :: "n"(N) : "memory");
}

// ---------------- K1a: masks + compaction ----------------
__global__ void mask_kernel(const int* __restrict__ x_ids,
                            const int* __restrict__ pad_p) {
    int b = blockIdx.x;
    int tid = threadIdx.x;           // 256 threads
    __shared__ unsigned char s_valid[LL];
    __shared__ int s_ired[256];
    int pad = *pad_p;
    int cnt = 0;
    for (int i = tid; i < LL; i += 256) {
        int v = (x_ids[b * LL + i] != pad) ? 1 : 0;
        s_valid[i] = (unsigned char)v;
        cnt += v;
    }
    s_ired[tid] = cnt;
    __syncthreads();
    for (int s = 128; s > 0; s >>= 1) {
        if (tid < s) s_ired[tid] += s_ired[tid + s];
        __syncthreads();
    }
    int vl = s_ired[0];
    int sep = vl / 2;
    if (sep < 1) sep = 1;
    if (sep > LL - 2) sep = LL - 2;
    if (tid == 0) {
        int nf = 0, no = 0;
        for (int i = 0; i < LL; i++) {
            if (s_valid[i]) {
                if (i < sep)      g_fIdx[b][nf++] = i;
                else if (i > sep) g_oIdx[b][no++] = i;
            }
        }
        g_nF[b] = nf;
        g_nO[b] = no;
    }
}

// ---------------- K1b: anomaly logits (raw, into g_gate) ----------------
__global__ void logit_kernel(const float* __restrict__ x,
                             const float* __restrict__ Wa,
                             const float* __restrict__ ba) {
    int b = blockIdx.x;
    int r = blockIdx.y * 256 + threadIdx.x;
    __shared__ float s_Wa[DD];
    for (int i = threadIdx.x; i < DD; i += 256) s_Wa[i] = Wa[i];
    __syncthreads();
    if (r >= g_nF[b]) return;
    const float* xr = x + ((size_t)b * LL + g_fIdx[b][r]) * DD;
    float acc = ba[0];
    #pragma unroll 8
    for (int k = 0; k < DD; k++) acc += xr[k] * s_Wa[k];
    g_gate[b][r] = acc;
}

// ---------------- K1c: gate softmax over nF logits ----------------
__global__ void gatesm_kernel() {
    int b = blockIdx.x;
    int tid = threadIdx.x;    // 256
    int nF = g_nF[b];
    if (nF == 0) return;
    __shared__ float red[256];
    __shared__ float s_logit[MAXF];
    for (int r = tid; r < nF; r += 256) s_logit[r] = g_gate[b][r];
    __syncthreads();
    float m = -1e30f;
    for (int r = tid; r < nF; r += 256) m = fmaxf(m, s_logit[r]);
    red[tid] = m; __syncthreads();
    for (int s = 128; s > 0; s >>= 1) { if (tid < s) red[tid] = fmaxf(red[tid], red[tid + s]); __syncthreads(); }
    float mx = red[0]; __syncthreads();
    float z = 0.f;
    for (int r = tid; r < nF; r += 256) z += expf(s_logit[r] - mx);
    red[tid] = z; __syncthreads();
    for (int s = 128; s > 0; s >>= 1) { if (tid < s) red[tid] += red[tid + s]; __syncthreads(); }
    float Z = red[0];
    for (int r = tid; r < nF; r += 256) g_gate[b][r] = expf(s_logit[r] - mx) / Z;
}

// ---------------- K2a: expand x -> [hi | lo] bf16 ----------------
__global__ void xexp_kernel(const float* __restrict__ x) {
    int row = blockIdx.x;            // b*1024 + l
    const float* src = x + (size_t)row * DD;
    __nv_bfloat16* dst = &g_Xexp[0][0][0] + (size_t)row * KEXP;
    for (int k = threadIdx.x; k < DD; k += 256) {
        float v = src[k];
        __nv_bfloat16 hi = __float2bfloat16(v);
        __nv_bfloat16 lo = __float2bfloat16(v - __bfloat162float(hi));
        dst[k] = hi; dst[DD + k] = lo;
    }
}

// ---------------- K2b: transpose + expand W -> [hi | lo] ----------------
__global__ void wexp_kernel(ProjPtrs pp) {
    int p = blockIdx.z;
    int k0 = blockIdx.y * 32, n0 = blockIdx.x * 32;
    __shared__ float tile[32][33];
    const float* W = pp.W[p];
    int tx = threadIdx.x & 31, ty = threadIdx.x >> 5;   // 32 x 8
    for (int i = ty; i < 32; i += 8) tile[i][tx] = W[(size_t)(k0 + i) * DD + n0 + tx];
    __syncthreads();
    for (int i = ty; i < 32; i += 8) {
        float v = tile[tx][i];   // = W[k0+tx][n0+i]
        __nv_bfloat16 hi = __float2bfloat16(v);
        __nv_bfloat16 lo = __float2bfloat16(v - __bfloat162float(hi));
        __nv_bfloat16* dst = &g_Wexp[p][n0 + i][0];
        dst[k0 + tx] = hi; dst[DD + k0 + tx] = lo;
    }
}

// ---------------- shared GEMM mainloop: 3-stage pipeline, swizzled 64B rows ----------------
// smem row layout: 4 x 16B chunks; chunk c16 stored at (c16 ^ ((row>>1)&3)).
// Combined block: A stages at [0, 3*SBUF), B stages at [BOFF, BOFF+3*SBUF). Total 48KB.
__device__ __forceinline__ void gemm3_loop(const char* aP, const char* bP,
                                           uint32_t sAu, uint32_t sBu,
                                           uint32_t st0, uint32_t st1,
                                           uint32_t aLdh, uint32_t aLdl,
                                           uint32_t bLdh, uint32_t bLdl,
                                           float acc[2][8][4]) {
    // prologue: stages 0,1
    #pragma unroll
    for (int s = 0; s < 2; s++) {
        uint32_t bo = s * SBUF;
        size_t go = (size_t)s * 32;
        cp16(sAu + bo + st0, aP + go); cp16(sAu + bo + st1, aP + go + 16);
        cp16(sBu + bo + st0, bP + go); cp16(sBu + bo + st1, bP + go + 16);
        cp_commit();
    }
    int buf = 0;
    for (int it = 0; it < NITER; it++) {
        cp_wait<1>();
        __syncthreads();
        if (it + 2 < NITER) {
            int nb = buf + 2; if (nb >= 3) nb -= 3;
            uint32_t bo = nb * SBUF;
            size_t go = (size_t)(it + 2) * 32;
            cp16(sAu + bo + st0, aP + go); cp16(sAu + bo + st1, aP + go + 16);
            cp16(sBu + bo + st0, bP + go); cp16(sBu + bo + st1, bP + go + 16);
        }
        cp_commit();   // empty group in drain iters keeps wait<1> accounting exact
        uint32_t aB = sAu + buf * SBUF;
        uint32_t bB = sBu + buf * SBUF;
        uint32_t afh[2][4], afl[2][4];
        ldsm_x4(afh[0], aB + aLdh);
        ldsm_x4(afh[1], aB + aLdh + 1024);
        ldsm_x4(afl[0], aB + aLdl);
        ldsm_x4(afl[1], aB + aLdl + 1024);
        #pragma unroll
        for (int j = 0; j < 4; j++) {
            uint32_t rh[4], rl[4];
            ldsm_x4(rh, bB + bLdh + j * 1024);
            ldsm_x4(rl, bB + bLdl + j * 1024);
            uint32_t bh0[2] = {rh[0], rh[1]}, bh1[2] = {rh[2], rh[3]};
            uint32_t bl0[2] = {rl[0], rl[1]}, bl1[2] = {rl[2], rl[3]};
            // term-major: same-acc reuse distance = 4 MMAs
            mma_bf16(acc[0][2 * j],     afh[0], bh0);
            mma_bf16(acc[0][2 * j + 1], afh[0], bh1);
            mma_bf16(acc[1][2 * j],     afh[1], bh0);
            mma_bf16(acc[1][2 * j + 1], afh[1], bh1);
            mma_bf16(acc[0][2 * j],     afh[0], bl0);
            mma_bf16(acc[0][2 * j + 1], afh[0], bl1);
            mma_bf16(acc[1][2 * j],     afh[1], bl0);
            mma_bf16(acc[1][2 * j + 1], afh[1], bl1);
            mma_bf16(acc[0][2 * j],     afl[0], bh0);
            mma_bf16(acc[0][2 * j + 1], afl[0], bh1);
            mma_bf16(acc[1][2 * j],     afl[1], bh0);
            mma_bf16(acc[1][2 * j + 1], afl[1], bh1);
        }
        buf++; if (buf == 3) buf = 0;
    }
}

// per-thread staging offsets (store side): row tid>>1, segment tid&1
__device__ __forceinline__ void stage_offsets(int tid, uint32_t& st0, uint32_t& st1) {
    int srow = tid >> 1, shalf = tid & 1;
    int s = (srow >> 1) & 3;
    st0 = srow * 64 + (((2 * shalf)     ^ s) * 16);
    st1 = srow * 64 + (((2 * shalf + 1) ^ s) * 16);
}
// ldmatrix offsets for A and B fragments (hi chunks 0/1, lo chunks 2/3, XOR-swizzled)
__device__ __forceinline__ void ld_offsets(int lane, int warp_m, int warp_n,
                                           uint32_t& aLdh, uint32_t& aLdl,
                                           uint32_t& bLdh, uint32_t& bLdl) {
    int a_row = warp_m * 32 + (lane & 7) + ((lane >> 3) & 1) * 8;
    int ch = (lane >> 4) & 1;
    int sa = (a_row >> 1) & 3;
    aLdh = a_row * 64 + ((ch ^ sa) * 16);
    aLdl = a_row * 64 + (((ch + 2) ^ sa) * 16);
    int b_row = warp_n * 64 + ((lane >> 4) & 1) * 8 + (lane & 7);
    int cb = (lane >> 3) & 1;
    int sb = (b_row >> 1) & 3;
    bLdh = b_row * 64 + ((cb ^ sb) * 16);
    bLdl = b_row * 64 + (((cb + 2) ^ sb) * 16);
}

// ---------------- K3: projection GEMMs ----------------
__global__ __launch_bounds__(256, 2) void proj_kernel(ProjPtrs pp) {
    int z = blockIdx.z; int p = z >> 3; int b = z & 7;
    bool isQ = (p < 3);
    int count = isQ ? g_nF[b] : g_nO[b];
    int m0 = blockIdx.y * 128;
    if (count == 0 || m0 >= count) return;
    int n0 = blockIdx.x * 128;   // N=768 -> 6 blocks
    const int* idx = isQ ? g_fIdx[b] : g_oIdx[b];

    __shared__ __align__(16) char smem[6 * SBUF];   // A: [0,3*SBUF)  B: [BOFF,...)

    int tid = threadIdx.x, lane = tid & 31, wid = tid >> 5;
    int warp_m = wid & 3, warp_n = wid >> 2;  // 4 x 2 warps -> 32x64 warp tile

    int srow = tid >> 1, shalf = tid & 1;
    int gm = m0 + srow; if (gm >= count) gm = count - 1;
    const char* aP = (const char*)&g_Xexp[b][0][0] + (size_t)idx[gm] * ROWB + shalf * SEGB;
    const char* bP = (const char*)&g_Wexp[p][0][0] + (size_t)(n0 + srow) * ROWB + shalf * SEGB;

    uint32_t st0, st1, aLdh, aLdl, bLdh, bLdl;
    stage_offsets(tid, st0, st1);
    ld_offsets(lane, warp_m, warp_n, aLdh, aLdl, bLdh, bLdl);
    uint32_t sAu = smem_u32(smem);
    uint32_t sBu = sAu + BOFF;

    float acc[2][8][4] = {};
    gemm3_loop(aP, bP, sAu, sBu, st0, st1, aLdh, aLdl, bLdh, bLdl, acc);

    // epilogue: bias + split to [hi | lo]
    const float* bias = pp.bias[p];
    __nv_bfloat16* outb = isQ ? &g_Qexp[p][b][0][0] : &g_Koexp[p - 3][b][0][0];
    int r0 = lane >> 2, cp = (lane & 3) * 2;
    #pragma unroll
    for (int mt = 0; mt < 2; mt++) {
        #pragma unroll
        for (int c2 = 0; c2 < 2; c2++) {
            int grow = m0 + warp_m * 32 + mt * 16 + r0 + c2 * 8;
            if (grow >= count) continue;
            char* dbase = (char*)(outb + (size_t)grow * KEXP);
            #pragma unroll
            for (int nt = 0; nt < 8; nt++) {
                int n = n0 + warp_n * 64 + nt * 8 + cp;
                float v0 = acc[mt][nt][c2 * 2 + 0] + bias[n];
                float v1 = acc[mt][nt][c2 * 2 + 1] + bias[n + 1];
                float h0 = __bfloat162float(__float2bfloat16(v0));
                float h1 = __bfloat162float(__float2bfloat16(v1));
                *(uint32_t*)(dbase + 2 * n) = packbf(v0, v1);
                *(uint32_t*)(dbase + 2 * (DD + n)) = packbf(v0 - h0, v1 - h1);
            }
        }
    }
}

// ---------------- K4: score GEMMs (Q @ Ko^T) ----------------
__global__ __launch_bounds__(256, 2) void score_kernel() {
    int z = blockIdx.z; int t = z >> 3; int b = z & 7;
    int nF = g_nF[b], nO = g_nO[b];
    int l0 = blockIdx.y * 128;
    if (nF == 0 || l0 >= nF) return;
    int m0 = blockIdx.x * 128;
    if (nO == 0 || m0 >= nO) return;

    __shared__ __align__(16) char smem[6 * SBUF];

    int tid = threadIdx.x, lane = tid & 31, wid = tid >> 5;
    int warp_m = wid & 3, warp_n = wid >> 2;

    int srow = tid >> 1, shalf = tid & 1;
    int rA = l0 + srow; if (rA >= nF) rA = nF - 1;
    int rB = m0 + srow; if (rB >= nO) rB = nO - 1;
    const char* aP = (const char*)&g_Qexp[t][b][0][0]  + (size_t)rA * ROWB + shalf * SEGB;
    const char* bP = (const char*)&g_Koexp[t][b][0][0] + (size_t)rB * ROWB + shalf * SEGB;

    uint32_t st0, st1, aLdh, aLdl, bLdh, bLdl;
    stage_offsets(tid, st0, st1);
    ld_offsets(lane, warp_m, warp_n, aLdh, aLdl, bLdh, bLdl);
    uint32_t sAu = smem_u32(smem);
    uint32_t sBu = sAu + BOFF;

    float acc[2][8][4] = {};
    gemm3_loop(aP, bP, sAu, sBu, st0, st1, aLdh, aLdl, bLdh, bLdl, acc);

    float* S = (t == 0) ? &g_Ssup[b][0][0] : (t == 1) ? &g_Scon[b][0][0] : &g_Srep[b][0][0];
    const float scale = 1.0f / sqrtf((float)DD);
    int r0 = lane >> 2, cp = (lane & 3) * 2;
    #pragma unroll
    for (int mt = 0; mt < 2; mt++) {
        #pragma unroll
        for (int c2 = 0; c2 < 2; c2++) {
            int l = l0 + warp_m * 32 + mt * 16 + r0 + c2 * 8;
            if (l >= nF) continue;
            float* Srow = S + (size_t)l * LL;
            #pragma unroll
            for (int nt = 0; nt < 8; nt++) {
                int m = m0 + warp_n * 64 + nt * 8 + cp;
                if (m < nO)     Srow[m]     = acc[mt][nt][c2 * 2 + 0] * scale;
                if (m + 1 < nO) Srow[m + 1] = acc[mt][nt][c2 * 2 + 1] * scale;
            }
        }
    }
}

// ---------------- K5: per-row softmax, write gate-weighted probs in place ----------------
__global__ void softmax_kernel() {
    int b = blockIdx.x;
    int l = blockIdx.y;
    if (l >= g_nF[b]) return;
    int nO = g_nO[b];
    if (nO == 0) return;
    int tid = threadIdx.x;   // 256
    __shared__ float red[256];
    float gate = g_gate[b][l];
    float* Ssup = &g_Ssup[b][l][0];
    float* Srep = &g_Srep[b][l][0];
    const float* Scon = &g_Scon[b][l][0];

    float sv[4], rv[4];
    #pragma unroll
    for (int r = 0; r < 4; r++) {
        int m = tid + r * 256;
        if (m < nO) {
            sv[r] = Ssup[m];
            rv[r] = Srep[m] + tanhf(Scon[m]);
        } else {
            sv[r] = -1e30f;
            rv[r] = -1e30f;
        }
    }
    float mx = fmaxf(fmaxf(sv[0], sv[1]), fmaxf(sv[2], sv[3]));
    red[tid] = mx; __syncthreads();
    for (int s = 128; s > 0; s >>= 1) { if (tid < s) red[tid] = fmaxf(red[tid], red[tid + s]); __syncthreads(); }
    mx = red[0]; __syncthreads();
    float e[4]; float z = 0.f;
    #pragma unroll
    for (int r = 0; r < 4; r++) { e[r] = expf(sv[r] - mx); z += e[r]; }
    red[tid] = z; __syncthreads();
    for (int s = 128; s > 0; s >>= 1) { if (tid < s) red[tid] += red[tid + s]; __syncthreads(); }
    float c = gate / red[0]; __syncthreads();
    #pragma unroll
    for (int r = 0; r < 4; r++) { int m = tid + r * 256; if (m < nO) Ssup[m] = e[r] * c; }
    mx = fmaxf(fmaxf(rv[0], rv[1]), fmaxf(rv[2], rv[3]));
    red[tid] = mx; __syncthreads();
    for (int s = 128; s > 0; s >>= 1) { if (tid < s) red[tid] = fmaxf(red[tid], red[tid + s]); __syncthreads(); }
    mx = red[0]; __syncthreads();
    z = 0.f;
    #pragma unroll
    for (int r = 0; r < 4; r++) { e[r] = expf(rv[r] - mx); z += e[r]; }
    red[tid] = z; __syncthreads();
    for (int s = 128; s > 0; s >>= 1) { if (tid < s) red[tid] += red[tid + s]; __syncthreads(); }
    c = gate / red[0];
    #pragma unroll
    for (int r = 0; r < 4; r++) { int m = tid + r * 256; if (m < nO) Srep[m] = e[r] * c; }
}

// ---------------- K6: column reduction, 8-way row-chunk split + combine ----------------
__global__ void colsum_part() {
    int b = blockIdx.x;
    int m = blockIdx.y * 256 + threadIdx.x;
    int c = blockIdx.z;
    int nF = g_nF[b];
    float a = 0.f, s = 0.f;
    int l0 = c * 64, l1 = min(l0 + 64, nF);
    for (int l = l0; l < l1; l++) {
        a += g_Ssup[b][l][m];
        s += g_Srep[b][l][m];
    }
    g_WsupP[c][b][m] = a;
    g_WrepP[c][b][m] = s;
}
__global__ void colsum_comb() {
    int b = blockIdx.x;
    int m = blockIdx.y * 256 + threadIdx.x;
    if (m >= g_nO[b]) return;
    float a = 0.f, s = 0.f;
    #pragma unroll
    for (int c = 0; c < 8; c++) { a += g_WsupP[c][b][m]; s += g_WrepP[c][b][m]; }
    g_Wsup[b][m] = a;
    g_Wrep[b][m] = s;
}

// ---------------- K7a: fused vectors, 8-way chunk split + combine ----------------
__global__ void fused_part(const float* __restrict__ x) {
    int b = blockIdx.x;
    int sec = blockIdx.y;     // 0=anomaly 1=wrep 2=wsup
    int c = blockIdx.z;
    int tid = threadIdx.x;    // 256, each thread 3 dims
    int nF = g_nF[b], nO = g_nO[b];
    const float* xb = x + (size_t)b * LL * DD;
    float acc[3] = {0.f, 0.f, 0.f};

    if (nF > 0) {
        if (sec == 0) {
            int i0 = c * 64, i1 = min(i0 + 64, nF);
            for (int i = i0; i < i1; i++) {
                float g = g_gate[b][i];
                const float* xr = xb + (size_t)g_fIdx[b][i] * DD;
                #pragma unroll
                for (int r = 0; r < 3; r++) acc[r] += g * xr[tid + r * 256];
            }
        } else if (nO > 0) {
            const float* w = (sec == 1) ? g_Wrep[b] : g_Wsup[b];
            int i0 = c * 128;
            int i1 = min(i0 + 128, nO);
            for (int i = i0; i < i1; i++) {
                float a = w[i];
                const float* xr = xb + (size_t)g_oIdx[b][i] * DD;
                #pragma unroll
                for (int r = 0; r < 3; r++) acc[r] += a * xr[tid + r * 256];
            }
        } else {
            int i0 = c * 128, i1 = i0 + 128;
            for (int i = i0; i < i1; i++) {
                const float* xr = xb + (size_t)i * DD;
                #pragma unroll
                for (int r = 0; r < 3; r++) acc[r] += xr[tid + r * 256] * (1.0f / (float)LL);
            }
        }
    }
    #pragma unroll
    for (int r = 0; r < 3; r++) g_fusedP[b][sec][c][tid + r * 256] = acc[r];
}
__global__ void fused_comb() {
    int b = blockIdx.x;
    int sec = blockIdx.y;
    int tid = threadIdx.x;
    #pragma unroll
    for (int r = 0; r < 3; r++) {
        int d = tid + r * 256;
        float s = 0.f;
        #pragma unroll
        for (int c = 0; c < 8; c++) s += g_fusedP[b][sec][c][d];
        g_fused[b][sec * DD + d] = s;
    }
}

// ---------------- K7b: h1 = relu(fused @ Wf1 + bf1), 4-way k-split ----------------
__global__ void h1_kernel(const float* __restrict__ Wf1, const float* __restrict__ bf1) {
    int b = blockIdx.x;
    int jc = blockIdx.y;     // 12 blocks of 64 outputs
    int tid = threadIdx.x;
    __shared__ float sf[3 * DD];
    __shared__ float red[256];
    for (int i = tid; i < 3 * DD; i += 256) sf[i] = g_fused[b][i];
    __syncthreads();
    int jloc = tid & 63, slice = tid >> 6;
    int j = jc * 64 + jloc;
    float acc = 0.f;
    int i0 = slice * 576;
    #pragma unroll 8
    for (int i = i0; i < i0 + 576; i++) acc += sf[i] * Wf1[(size_t)i * DD + j];
    red[tid] = acc;
    __syncthreads();
    if (tid < 64) {
        float s = red[tid] + red[tid + 64] + red[tid + 128] + red[tid + 192] + bf1[jc * 64 + tid];
        g_h1[b][jc * 64 + tid] = fmaxf(s, 0.0f);
    }
}

// ---------------- K7c: h2 = h1 @ Wf2 + bf2, then layernorm ----------------
__global__ void h2ln_kernel(const float* __restrict__ Wf2, const float* __restrict__ bf2,
                            const float* __restrict__ gamma, const float* __restrict__ beta,
                            float* __restrict__ out) {
    int b = blockIdx.x;
    int tid = threadIdx.x;   // 256, each thread 3 dims
    __shared__ float h1s[DD];
    __shared__ float red[256];
    for (int i = tid; i < DD; i += 256) h1s[i] = g_h1[b][i];
    __syncthreads();

    float h2[3];
    #pragma unroll
    for (int r = 0; r < 3; r++) h2[r] = bf2[tid + r * 256];
    #pragma unroll 8
    for (int i = 0; i < DD; i++) {
        float f = h1s[i];
        #pragma unroll
        for (int r = 0; r < 3; r++) h2[r] += f * Wf2[(size_t)i * DD + tid + r * 256];
    }

    float s = h2[0] + h2[1] + h2[2];
    red[tid] = s; __syncthreads();
    for (int st = 128; st > 0; st >>= 1) { if (tid < st) red[tid] += red[tid + st]; __syncthreads(); }
    float mu = red[0] / (float)DD;
    __syncthreads();
    float v = 0.f;
    #pragma unroll
    for (int r = 0; r < 3; r++) { float dlt = h2[r] - mu; v += dlt * dlt; }
    red[tid] = v; __syncthreads();
    for (int st = 128; st > 0; st >>= 1) { if (tid < st) red[tid] += red[tid + st]; __syncthreads(); }
    float inv = rsqrtf(red[0] / (float)DD + 1e-5f);
    #pragma unroll
    for (int r = 0; r < 3; r++) {
        int j = tid + r * 256;
        out[(size_t)b * DD + j] = (h2[r] - mu) * inv * gamma[j] + beta[j];
    }
}

// ---------------- launch ----------------
extern "C" void kernel_launch(void* const* d_in, const int* in_sizes, int n_in,
                              void* d_out, int out_size) {
    (void)in_sizes; (void)n_in; (void)out_size;
    const float* x     = (const float*)d_in[0];
    const int*   x_ids = (const int*)d_in[1];
    const int*   pad   = (const int*)d_in[2];
    const float* Wa    = (const float*)d_in[3];
    const float* ba    = (const float*)d_in[4];

    ProjPtrs pp;
    pp.W[0] = (const float*)d_in[5];  pp.bias[0] = (const float*)d_in[6];   // qs
    pp.W[1] = (const float*)d_in[9];  pp.bias[1] = (const float*)d_in[10];  // qc
    pp.W[2] = (const float*)d_in[13]; pp.bias[2] = (const float*)d_in[14];  // qr
    pp.W[3] = (const float*)d_in[7];  pp.bias[3] = (const float*)d_in[8];   // ks
    pp.W[4] = (const float*)d_in[11]; pp.bias[4] = (const float*)d_in[12];  // kc
    pp.W[5] = (const float*)d_in[15]; pp.bias[5] = (const float*)d_in[16];  // kr

    mask_kernel<<<BB, 256>>>(x_ids, pad);
    logit_kernel<<<dim3(BB, 2), 256>>>(x, Wa, ba);
    gatesm_kernel<<<BB, 256>>>();
    xexp_kernel<<<BB * LL, 256>>>(x);
    wexp_kernel<<<dim3(24, 24, 6), 256>>>(pp);
    proj_kernel<<<dim3(6, 8, 48), 256>>>(pp);
    score_kernel<<<dim3(8, 4, 24), 256>>>();
    softmax_kernel<<<dim3(BB, MAXF), 256>>>();
    colsum_part<<<dim3(BB, LL / 256, 8), 256>>>();
    colsum_comb<<<dim3(BB, LL / 256), 256>>>();
    fused_part<<<dim3(BB, 3, 8), 256>>>(x);
    fused_comb<<<dim3(BB, 3), 256>>>();
    h1_kernel<<<dim3(BB, 12), 256>>>((const float*)d_in[17], (const float*)d_in[18]);
    h2ln_kernel<<<BB, 256>>>((const float*)d_in[19], (const float*)d_in[20],
                             (const float*)d_in[21], (const float*)d_in[22],
                             (float*)d_out);
}